// round 12
// baseline (speedup 1.0000x reference)
#include <cuda_runtime.h>
#include <math.h>

#define BB    8
#define NN    107136
#define PRE   2048
#define POST  128
#define CAND  6144   // bin-floor candidates ~4600
#define CAND2 3072   // exact-threshold survivors ~2050 (+ties)
#define WPB   32     // 64-bit words per row mask (PRE/64)
#define HB    65536  // 16-bit histogram bins

typedef unsigned long long ull;

// ---------------- scratch (static __device__, no allocations) ----------------
// hist16 is self-cleaning: scan_kernel zeroes it after reading, so every graph
// replay starts from a zeroed histogram (static init is also zero).
static __device__ unsigned g_skey[BB * NN];
static __device__ unsigned g_hist16[BB * HB];
static __device__ unsigned g_thresh[BB];
static __device__ int      g_target[BB];
static __device__ ull      g_cand[BB * CAND];
static __device__ int      g_cand_cnt[BB];
static __device__ ull      g_topkeys[BB * PRE];
static __device__ float    g_boxes[BB * PRE * 7];
static __device__ float4   g_bb4[BB * PRE];
static __device__ int      g_dl[BB * PRE];
static __device__ ull      g_supmask[(size_t)BB * PRE * WPB];
static __device__ ull      g_validmask[BB * WPB];

// ---------------- 1) scores -> keys + 16-bit histogram (ONE expf/elem) ------
__global__ void score_hist_kernel(const float4* __restrict__ cls) {
    int i = blockIdx.x * blockDim.x + threadIdx.x;   // pair index
    if (i >= BB * NN / 2) return;
    int b = (2 * i) / NN;
    float4 c = cls[i];
    float p0, p1;
    {
        float d = c.y - c.x;
        if (d <= 0.0f) { float e = expf(d);  p0 = e / (1.0f + e); }
        else           { float e = expf(-d); p0 = 1.0f / (e + 1.0f); }
    }
    {
        float d = c.w - c.z;
        if (d <= 0.0f) { float e = expf(d);  p1 = e / (1.0f + e); }
        else           { float e = expf(-d); p1 = 1.0f / (e + 1.0f); }
    }
    unsigned k0 = (p0 >= 0.05f) ? __float_as_uint(p0) : 0u;
    unsigned k1 = (p1 >= 0.05f) ? __float_as_uint(p1) : 0u;
    ((uint2*)g_skey)[i] = make_uint2(k0, k1);
    if (k0) atomicAdd(&g_hist16[b * HB + (k0 >> 16)], 1u);
    if (k1) atomicAdd(&g_hist16[b * HB + (k1 >> 16)], 1u);
}

// ---------------- 2) crossing-bin search + state reset + self-clean ---------
__global__ void __launch_bounds__(1024) scan_kernel() {
    int b = blockIdx.x, tid = threadIdx.x;
    int lane = tid & 31, wid = tid >> 5;
    __shared__ unsigned wsum[32];
    __shared__ unsigned wsuf[32];
    __shared__ unsigned s_total;

    // reset per-batch state consumed by LATER phases of this replay
    if (tid == 0) g_cand_cnt[b] = 0;
    if (tid < WPB) g_validmask[b * WPB + tid] = 0ull;
    for (int i = tid; i < PRE; i += 1024) g_topkeys[(size_t)b * PRE + i] = 0ull;

    const uint4* h4 = (const uint4*)(g_hist16 + b * HB);
    unsigned tsum = 0;
#pragma unroll
    for (int j = 0; j < 16; ++j) {
        uint4 v = h4[tid * 16 + j];
        tsum += v.x + v.y + v.z + v.w;
    }
    unsigned s = tsum;
#pragma unroll
    for (int off = 1; off < 32; off <<= 1) {
        unsigned o = __shfl_down_sync(0xFFFFFFFFu, s, off);
        if (lane + off < 32) s += o;
    }
    if (lane == 0) wsum[wid] = s;
    __syncthreads();
    if (tid < 32) {
        unsigned t = wsum[tid];
        unsigned e = t;
#pragma unroll
        for (int off = 1; off < 32; off <<= 1) {
            unsigned o = __shfl_down_sync(0xFFFFFFFFu, e, off);
            if (tid + off < 32) e += o;
        }
        wsuf[tid] = e - t;
        if (tid == 0) s_total = e;
    }
    __syncthreads();
    if (tid == 0 && s_total < PRE) { g_thresh[b] = 1u; g_target[b] = 0; }  // take-all
    unsigned above = wsuf[wid] + (s - tsum);
    if (above < PRE && above + tsum >= PRE) {          // unique crossing thread
        unsigned run = above;
        int found = -1;
        for (int j = 15; j >= 0 && found < 0; --j) {
            uint4 v = h4[tid * 16 + j];
            unsigned a[4] = {v.x, v.y, v.z, v.w};
            for (int q = 3; q >= 0; --q) {
                if (run + a[q] >= PRE) { found = tid * 64 + j * 4 + q; break; }
                run += a[q];
            }
        }
        g_thresh[b] = ((unsigned)found) << 16;         // 16-bit bin floor
        g_target[b] = PRE - (int)run;                  // needed from crossing bin
    }
    __syncthreads();
    // self-clean histogram for the next replay
    uint4 z = make_uint4(0u, 0u, 0u, 0u);
    uint4* h4w = (uint4*)(g_hist16 + b * HB);
#pragma unroll
    for (int j = 0; j < 16; ++j) h4w[tid * 16 + j] = z;
}

// ---------------- 3) compact candidates (vec4 + warp-aggregated atomic) -----
__global__ void compact_kernel() {
    int i4 = blockIdx.x * blockDim.x + threadIdx.x;
    if (i4 >= BB * NN / 4) return;
    int e0 = i4 * 4;
    int b = e0 / NN;                  // NN % 128 == 0 -> warp-uniform
    unsigned thresh = g_thresh[b];
    uint4 kv = ((const uint4*)g_skey)[i4];
    unsigned k[4] = {kv.x, kv.y, kv.z, kv.w};
    ull loc[4]; int nh = 0;
    unsigned base_i = (unsigned)(e0 - b * NN);
#pragma unroll
    for (int q = 0; q < 4; ++q) {
        if (k[q] && k[q] >= thresh)
            loc[nh++] = ((ull)k[q] << 32) | (ull)(0xFFFFFFFFu - (base_i + q));
    }
    int lane = threadIdx.x & 31;
    int pre = nh;
#pragma unroll
    for (int off = 1; off < 32; off <<= 1) {
        int o = __shfl_up_sync(0xFFFFFFFFu, pre, off);
        if (lane >= off) pre += o;
    }
    int tot = __shfl_sync(0xFFFFFFFFu, pre, 31);
    pre -= nh;
    int base = 0;
    if (lane == 31 && tot > 0) base = atomicAdd(&g_cand_cnt[b], tot);
    base = __shfl_sync(0xFFFFFFFFu, base, 31);
    for (int q = 0; q < nh; ++q) {
        int p = base + pre + q;
        if (p < CAND) g_cand[b * CAND + p] = loc[q];
    }
}

// ---------------- 4) fused refine (exact 32-bit thresh) + filtered rank -----
__global__ void __launch_bounds__(1024) rank2_kernel() {
    int b = blockIdx.x, tid = threadIdx.x;
    __shared__ __align__(16) ull sk2[CAND2];   // 24KB survivors
    __shared__ unsigned h1[256];
    __shared__ int s_cnt2;
    __shared__ unsigned s_c1, s_t1, s_thresh;

    int cnt = g_cand_cnt[b]; if (cnt > CAND) cnt = CAND;
    if (cnt <= 0) return;                      // topkeys already zeroed by scan
    const ull* cand = g_cand + b * CAND;
    unsigned bf = g_thresh[b];

    if (tid < 256) h1[tid] = 0u;
    if (tid == 0) { s_cnt2 = 0; s_thresh = 0u; s_c1 = 0u; s_t1 = 0u; }
    __syncthreads();

    if (bf > 1u) {
        unsigned targ = (unsigned)g_target[b];
        // level 1: histogram of bits [15:8] within the crossing 16-bit bin
        for (int i = tid; i < cnt; i += 1024) {
            unsigned k = (unsigned)(cand[i] >> 32);
            if ((k & 0xFFFF0000u) == bf) atomicAdd(&h1[(k >> 8) & 255], 1u);
        }
        __syncthreads();
        if (tid < 32) {                        // warp-parallel suffix walk
            unsigned a[8]; unsigned lsum = 0;
#pragma unroll
            for (int j = 0; j < 8; ++j) { a[j] = h1[tid * 8 + j]; lsum += a[j]; }
            unsigned s = lsum;
#pragma unroll
            for (int off = 1; off < 32; off <<= 1) {
                unsigned o = __shfl_down_sync(0xFFFFFFFFu, s, off);
                if (tid + off < 32) s += o;
            }
            unsigned above = s - lsum;         // count in higher lanes' bins
            if (above < targ && above + lsum >= targ) {   // unique crossing lane
                unsigned run = above;
                for (int j = 7; j >= 0; --j) {
                    if (run + a[j] >= targ) { s_c1 = (unsigned)(tid * 8 + j); s_t1 = targ - run; break; }
                    run += a[j];
                }
            }
        }
        __syncthreads();
        unsigned pref = bf | (s_c1 << 8);
        unsigned t1 = s_t1;
        if (tid < 256) h1[tid] = 0u;
        __syncthreads();
        // level 2: histogram of bits [7:0] within the crossing 24-bit prefix
        for (int i = tid; i < cnt; i += 1024) {
            unsigned k = (unsigned)(cand[i] >> 32);
            if ((k & 0xFFFFFF00u) == pref) atomicAdd(&h1[k & 255], 1u);
        }
        __syncthreads();
        if (tid < 32) {
            unsigned a[8]; unsigned lsum = 0;
#pragma unroll
            for (int j = 0; j < 8; ++j) { a[j] = h1[tid * 8 + j]; lsum += a[j]; }
            unsigned s = lsum;
#pragma unroll
            for (int off = 1; off < 32; off <<= 1) {
                unsigned o = __shfl_down_sync(0xFFFFFFFFu, s, off);
                if (tid + off < 32) s += o;
            }
            unsigned above = s - lsum;
            if (above < t1 && above + lsum >= t1) {
                unsigned run = above;
                for (int j = 7; j >= 0; --j) {
                    if (run + a[j] >= t1) { s_thresh = pref | (unsigned)(tid * 8 + j); break; }
                    run += a[j];
                }
            }
        }
        __syncthreads();
    }
    unsigned th = s_thresh;                    // 0 when take-all

    // compact survivors into smem (order-free: rank is a multiset count)
    for (int i = tid; i < cnt; i += 1024) {
        ull key = cand[i];
        if ((unsigned)(key >> 32) >= th) {
            int p = atomicAdd(&s_cnt2, 1);
            if (p < CAND2) sk2[p] = key;
        }
    }
    __syncthreads();
    int cnt2 = s_cnt2; if (cnt2 > CAND2) cnt2 = CAND2;

    // filtered quadratic rank: survivors vs survivors only
    for (int i = tid; i < cnt; i += 1024) {
        ull mine = cand[i];
        if ((unsigned)(mine >> 32) < th) continue;   // below thresh: rank >= PRE
        int rank = 0, j = 0;
        for (; j + 4 <= cnt2; j += 4) {
            rank += (sk2[j]     > mine);
            rank += (sk2[j + 1] > mine);
            rank += (sk2[j + 2] > mine);
            rank += (sk2[j + 3] > mine);
        }
        for (; j < cnt2; ++j) rank += (sk2[j] > mine);
        if (rank < PRE) g_topkeys[(size_t)b * PRE + rank] = mine;
    }
}

// ---------------- 5) decode selected boxes ----------------
__global__ void decode_kernel(const float* __restrict__ boxp,
                              const float* __restrict__ dirp,
                              const float* __restrict__ anch) {
    int i = blockIdx.x * blockDim.x + threadIdx.x;
    if (i >= BB * PRE) return;
    int b = i / PRE, r = i % PRE;
    ull key = g_topkeys[i];
    unsigned skey = (unsigned)(key >> 32);

    float o[7] = {0.f, 0.f, 0.f, 0.f, 0.f, 0.f, 0.f};
    float4 bb = make_float4(0.f, 0.f, 0.f, 0.f);
    int dl = 0;

    if (skey) {
        unsigned idx = 0xFFFFFFFFu - (unsigned)(key & 0xFFFFFFFFull);
        size_t base = ((size_t)b * NN + idx) * 7;
        float xa = anch[base + 0], ya = anch[base + 1], za = anch[base + 2];
        float wa = anch[base + 3], la = anch[base + 4], ha = anch[base + 5];
        float ra = anch[base + 6];
        float xt = boxp[base + 0], yt = boxp[base + 1], zt = boxp[base + 2];
        float wt = boxp[base + 3], lt = boxp[base + 4], ht = boxp[base + 5];
        float rt = boxp[base + 6];

        za = za + ha * 0.5f;
        float diag = sqrtf(la * la + wa * wa);
        float xg = xt * diag + xa;
        float yg = yt * diag + ya;
        float zg = zt * ha + za;
        float lg = expf(lt) * la;
        float wg = expf(wt) * wa;
        float hg = expf(ht) * ha;
        float rg = rt + ra;
        zg = zg - hg * 0.5f;

        o[0] = xg; o[1] = yg; o[2] = zg; o[3] = wg; o[4] = lg; o[5] = hg; o[6] = rg;

        float cc = fabsf(cosf(rg)), ss = fabsf(sinf(rg));
        float hx = 0.5f * (wg * cc + lg * ss);
        float hy = 0.5f * (wg * ss + lg * cc);
        bb = make_float4(xg - hx, yg - hy, xg + hx, yg + hy);

        size_t dbase = ((size_t)b * NN + idx) * 2;
        dl = (dirp[dbase + 1] > dirp[dbase + 0]) ? 1 : 0;

        atomicOr(&g_validmask[b * WPB + (r >> 6)], 1ull << (r & 63));
    }
#pragma unroll
    for (int j = 0; j < 7; ++j) g_boxes[(size_t)i * 7 + j] = o[j];
    g_bb4[i] = bb;
    g_dl[i] = dl;
}

// ---------------- 6) pairwise IoU bit-matrix (upper triangle, ballot) -------
__global__ void __launch_bounds__(256) iou_kernel() {
    int p = blockIdx.x;          // triangular pair index [0, 528)
    int b = blockIdx.y;
    int rb = (int)((65.0f - sqrtf(4225.0f - 8.0f * (float)p)) * 0.5f);
    while (rb * (65 - rb) / 2 > p) --rb;
    while ((rb + 1) * (64 - rb) / 2 <= p) ++rb;
    int cb = rb + (p - rb * (65 - rb) / 2);

    int t = threadIdx.x;
    __shared__ float4 scol[64]; __shared__ float sca[64];
    __shared__ float4 srow[64]; __shared__ float sra[64];
    if (t < 64) {
        float4 c = g_bb4[(size_t)b * PRE + cb * 64 + t];
        scol[t] = c; sca[t] = (c.z - c.x) * (c.w - c.y);
    } else if (t < 128) {
        int r = t - 64;
        float4 c = g_bb4[(size_t)b * PRE + rb * 64 + r];
        srow[r] = c; sra[r] = (c.z - c.x) * (c.w - c.y);
    }
    __syncthreads();

    int wid = t >> 5, lane = t & 31;
#pragma unroll
    for (int rr = 0; rr < 8; ++rr) {
        int r = wid * 8 + rr;
        int grow = rb * 64 + r;
        float4 rbx = srow[r];
        float  ra  = sra[r];
        ull bits = 0ull;
#pragma unroll
        for (int h = 0; h < 2; ++h) {
            int c = h * 32 + lane;
            int gcol = cb * 64 + c;
            float4 cc = scol[c];
            float ix = fmaxf(0.f, fminf(rbx.z, cc.z) - fmaxf(rbx.x, cc.x));
            float iy = fmaxf(0.f, fminf(rbx.w, cc.w) - fmaxf(rbx.y, cc.y));
            float inter = ix * iy;
            float denom = fmaxf(ra + sca[c] - inter, 1e-8f);
            bool sup = (gcol > grow) && (inter > 0.5f * denom);
            unsigned m = __ballot_sync(0xFFFFFFFFu, sup);
            bits |= (ull)m << (h * 32);
        }
        if (lane == 0)
            g_supmask[((size_t)b * PRE + grow) * WPB + cb] = bits;
    }
}

// ---------------- 7) Jacobi-fixpoint greedy NMS + output (exact) ------------
__global__ void __launch_bounds__(1024) nms_out_kernel(float* __restrict__ out) {
    int b = blockIdx.x, tid = threadIdx.x;
    int w = tid & 31, rg = tid >> 5;   // word index, 64-row group index
    __shared__ ull s_keep[WPB], s_valid[WPB];
    __shared__ ull s_part[WPB][WPB + 1];
    __shared__ int s_flag;
    __shared__ int s_sel[POST];
    __shared__ int s_cnt;

    if (tid < WPB) {
        ull v = g_validmask[b * WPB + tid];
        s_valid[tid] = v;
        s_keep[tid] = v;
    }
    __syncthreads();

    const ull* rowbase = &g_supmask[((size_t)b * PRE + rg * 64) * WPB + w];

    for (int iter = 0; iter < PRE; ++iter) {
        ull acc = 0ull;
        if (w >= rg) {                 // only upper-triangle words are non-zero
            ull kw = s_keep[rg];
#pragma unroll 8
            for (int r = 0; r < 64; ++r)
                if ((kw >> r) & 1ull) acc |= rowbase[(size_t)r * WPB];
        }
        s_part[rg][w] = acc;
        if (tid == 0) s_flag = 0;
        __syncthreads();
        if (tid < WPB) {
            ull o = 0ull;
#pragma unroll
            for (int g = 0; g < WPB; ++g) o |= s_part[g][tid];
            ull nk = s_valid[tid] & ~o;
            if (nk != s_keep[tid]) s_flag = 1;
            s_keep[tid] = nk;
        }
        __syncthreads();
        if (!s_flag) break;
    }

    if (tid == 0) {
        int cnt = 0;
        for (int ww = 0; ww < WPB && cnt < POST; ++ww) {
            ull m = s_keep[ww];
            while (m && cnt < POST) {
                int r = __ffsll((long long)m) - 1;
                m &= m - 1;
                s_sel[cnt++] = ww * 64 + r;
            }
        }
        s_cnt = cnt;
    }
    __syncthreads();

    if (tid < POST) {
        float o0 = 0.f, o1 = 0.f, o2 = 0.f, o3 = 0.f, o4 = 0.f, o5 = 0.f, o6 = 0.f;
        float os = 0.f, om = 0.f;
        if (tid < s_cnt) {
            int r = s_sel[tid];
            const float* bx = &g_boxes[((size_t)b * PRE + r) * 7];
            float x = bx[0], y = bx[1], z = bx[2];
            float wd = bx[3], l = bx[4], h = bx[5], rgr = bx[6];
            float score = __uint_as_float((unsigned)(g_topkeys[(size_t)b * PRE + r] >> 32));
            int dl = g_dl[b * PRE + r];
            const float period = 3.14159265358979323846f;   // 2*pi/NUM_DIR_BINS
            float dir_rot = rgr - floorf(rgr / period) * period;
            float new_r = dir_rot + period * (float)dl;
            bool in_range = (x >= 0.0f) && (y >= -39.68f) && (z >= -5.0f) &&
                            (x <= 69.12f) && (y <= 39.68f) && (z <= 5.0f);
            if (in_range) {
                o0 = x; o1 = y; o2 = z; o3 = wd; o4 = l; o5 = h; o6 = new_r;
                os = score; om = 1.0f;
            }
        }
        size_t bo = (size_t)b * POST + tid;
        out[bo * 7 + 0] = o0; out[bo * 7 + 1] = o1; out[bo * 7 + 2] = o2;
        out[bo * 7 + 3] = o3; out[bo * 7 + 4] = o4; out[bo * 7 + 5] = o5;
        out[bo * 7 + 6] = o6;
        out[BB * POST * 7 + bo]                 = os;   // scores
        out[BB * POST * 7 + BB * POST + bo]     = 0.0f; // labels
        out[BB * POST * 7 + 2 * BB * POST + bo] = om;   // mask
    }
}

// ---------------- launcher: 7 plain launches ----------------
extern "C" void kernel_launch(void* const* d_in, const int* in_sizes, int n_in,
                              void* d_out, int out_size) {
    const float* boxp = (const float*)d_in[0];   // (B,N,7)
    const float* clsp = (const float*)d_in[1];   // (B,N,2)
    const float* dirp = (const float*)d_in[2];   // (B,N,2)
    const float* anch = (const float*)d_in[3];   // (B,N,7)
    float* out = (float*)d_out;

    score_hist_kernel<<<(BB * NN / 2 + 255) / 256, 256>>>((const float4*)clsp);
    scan_kernel<<<BB, 1024>>>();
    compact_kernel<<<(BB * NN / 4 + 255) / 256, 256>>>();
    rank2_kernel<<<BB, 1024>>>();
    decode_kernel<<<(BB * PRE + 127) / 128, 128>>>(boxp, dirp, anch);
    dim3 giou(528, BB);
    iou_kernel<<<giou, 256>>>();
    nms_out_kernel<<<BB, 1024>>>(out);
}

// round 13
// speedup vs baseline: 1.5651x; 1.5651x over previous
#include <cuda_runtime.h>
#include <math.h>

#define BB    8
#define NN    107136
#define PRE   2048
#define POST  128
#define CAND  6144   // bin-floor candidates ~4600
#define CAND2 3072   // exact-threshold survivors ~2050 (+ties)
#define WPB   32     // 64-bit words per row mask (PRE/64)
#define HB    65536  // 16-bit histogram bins

typedef unsigned long long ull;

// ---------------- scratch (static __device__, no allocations) ----------------
// hist16 is self-cleaning: scan_kernel zeroes it after reading, so every graph
// replay starts from a zeroed histogram (static init is also zero).
static __device__ unsigned g_skey[BB * NN];
static __device__ unsigned g_hist16[BB * HB];
static __device__ unsigned g_thresh[BB];
static __device__ int      g_target[BB];
static __device__ ull      g_cand[BB * CAND];
static __device__ int      g_cand_cnt[BB];
static __device__ ull      g_topkeys[BB * PRE];
static __device__ float    g_boxes[BB * PRE * 7];
static __device__ float4   g_bb4[BB * PRE];
static __device__ int      g_dl[BB * PRE];
static __device__ ull      g_supmask[(size_t)BB * PRE * WPB];
static __device__ ull      g_validmask[BB * WPB];

// ---------------- 1) scores -> keys + 16-bit histogram (ONE expf/elem) ------
__global__ void score_hist_kernel(const float4* __restrict__ cls) {
    int i = blockIdx.x * blockDim.x + threadIdx.x;   // pair index
    if (i >= BB * NN / 2) return;
    int b = (2 * i) / NN;
    float4 c = cls[i];
    float p0, p1;
    {
        float d = c.y - c.x;
        if (d <= 0.0f) { float e = expf(d);  p0 = e / (1.0f + e); }
        else           { float e = expf(-d); p0 = 1.0f / (e + 1.0f); }
    }
    {
        float d = c.w - c.z;
        if (d <= 0.0f) { float e = expf(d);  p1 = e / (1.0f + e); }
        else           { float e = expf(-d); p1 = 1.0f / (e + 1.0f); }
    }
    unsigned k0 = (p0 >= 0.05f) ? __float_as_uint(p0) : 0u;
    unsigned k1 = (p1 >= 0.05f) ? __float_as_uint(p1) : 0u;
    ((uint2*)g_skey)[i] = make_uint2(k0, k1);
    if (k0) atomicAdd(&g_hist16[b * HB + (k0 >> 16)], 1u);
    if (k1) atomicAdd(&g_hist16[b * HB + (k1 >> 16)], 1u);
}

// ---------------- 2) crossing-bin search + state reset + self-clean ---------
__global__ void __launch_bounds__(1024) scan_kernel() {
    int b = blockIdx.x, tid = threadIdx.x;
    int lane = tid & 31, wid = tid >> 5;
    __shared__ unsigned wsum[32];
    __shared__ unsigned wsuf[32];
    __shared__ unsigned s_total;

    // reset per-batch state consumed by LATER phases of this replay
    if (tid == 0) g_cand_cnt[b] = 0;
    if (tid < WPB) g_validmask[b * WPB + tid] = 0ull;
    for (int i = tid; i < PRE; i += 1024) g_topkeys[(size_t)b * PRE + i] = 0ull;

    const uint4* h4 = (const uint4*)(g_hist16 + b * HB);
    unsigned tsum = 0;
#pragma unroll
    for (int j = 0; j < 16; ++j) {
        uint4 v = h4[tid * 16 + j];
        tsum += v.x + v.y + v.z + v.w;
    }
    unsigned s = tsum;
#pragma unroll
    for (int off = 1; off < 32; off <<= 1) {
        unsigned o = __shfl_down_sync(0xFFFFFFFFu, s, off);
        if (lane + off < 32) s += o;
    }
    if (lane == 0) wsum[wid] = s;
    __syncthreads();
    if (tid < 32) {
        unsigned t = wsum[tid];
        unsigned e = t;
#pragma unroll
        for (int off = 1; off < 32; off <<= 1) {
            unsigned o = __shfl_down_sync(0xFFFFFFFFu, e, off);
            if (tid + off < 32) e += o;
        }
        wsuf[tid] = e - t;
        if (tid == 0) s_total = e;
    }
    __syncthreads();
    if (tid == 0 && s_total < PRE) { g_thresh[b] = 1u; g_target[b] = 0; }  // take-all
    unsigned above = wsuf[wid] + (s - tsum);
    if (above < PRE && above + tsum >= PRE) {          // unique crossing thread
        unsigned run = above;
        int found = -1;
        for (int j = 15; j >= 0 && found < 0; --j) {
            uint4 v = h4[tid * 16 + j];
            unsigned a[4] = {v.x, v.y, v.z, v.w};
            for (int q = 3; q >= 0; --q) {
                if (run + a[q] >= PRE) { found = tid * 64 + j * 4 + q; break; }
                run += a[q];
            }
        }
        g_thresh[b] = ((unsigned)found) << 16;         // 16-bit bin floor
        g_target[b] = PRE - (int)run;                  // needed from crossing bin
    }
    __syncthreads();
    // self-clean histogram for the next replay
    uint4 z = make_uint4(0u, 0u, 0u, 0u);
    uint4* h4w = (uint4*)(g_hist16 + b * HB);
#pragma unroll
    for (int j = 0; j < 16; ++j) h4w[tid * 16 + j] = z;
}

// ---------------- 3) compact candidates (vec4 + warp-aggregated atomic) -----
__global__ void compact_kernel() {
    int i4 = blockIdx.x * blockDim.x + threadIdx.x;
    if (i4 >= BB * NN / 4) return;
    int e0 = i4 * 4;
    int b = e0 / NN;                  // NN % 128 == 0 -> warp-uniform
    unsigned thresh = g_thresh[b];
    uint4 kv = ((const uint4*)g_skey)[i4];
    unsigned k[4] = {kv.x, kv.y, kv.z, kv.w};
    ull loc[4]; int nh = 0;
    unsigned base_i = (unsigned)(e0 - b * NN);
#pragma unroll
    for (int q = 0; q < 4; ++q) {
        if (k[q] && k[q] >= thresh)
            loc[nh++] = ((ull)k[q] << 32) | (ull)(0xFFFFFFFFu - (base_i + q));
    }
    int lane = threadIdx.x & 31;
    int pre = nh;
#pragma unroll
    for (int off = 1; off < 32; off <<= 1) {
        int o = __shfl_up_sync(0xFFFFFFFFu, pre, off);
        if (lane >= off) pre += o;
    }
    int tot = __shfl_sync(0xFFFFFFFFu, pre, 31);
    pre -= nh;
    int base = 0;
    if (lane == 31 && tot > 0) base = atomicAdd(&g_cand_cnt[b], tot);
    base = __shfl_sync(0xFFFFFFFFu, base, 31);
    for (int q = 0; q < nh; ++q) {
        int p = base + pre + q;
        if (p < CAND) g_cand[b * CAND + p] = loc[q];
    }
}

// ---------------- 4) redundant-refine + filtered rank (192 CTAs) ------------
// Each CTA independently computes the exact 32-bit threshold (cheap: two
// histogram passes over L2-resident candidates + warp suffix walks), filters
// survivors into smem, then ranks its 256-candidate slice against survivors.
__global__ void __launch_bounds__(256) rank3_kernel() {
    int b = blockIdx.y, tid = threadIdx.x;
    __shared__ __align__(16) ull sk2[CAND2];   // 24KB survivors
    __shared__ unsigned h1[256];
    __shared__ int s_cnt2;
    __shared__ unsigned s_c1, s_t1, s_thresh;

    int cnt = g_cand_cnt[b]; if (cnt > CAND) cnt = CAND;
    if (cnt <= 0) return;                      // topkeys already zeroed by scan
    if (blockIdx.x * 256 >= cnt) return;       // idle slice
    const ull* cand = g_cand + b * CAND;
    unsigned bf = g_thresh[b];

    h1[tid] = 0u;
    if (tid == 0) { s_cnt2 = 0; s_thresh = 0u; s_c1 = 0u; s_t1 = 0u; }
    __syncthreads();

    if (bf > 1u) {
        unsigned targ = (unsigned)g_target[b];
        // level 1: histogram of bits [15:8] within the crossing 16-bit bin
        for (int i = tid; i < cnt; i += 256) {
            unsigned k = (unsigned)(cand[i] >> 32);
            if ((k & 0xFFFF0000u) == bf) atomicAdd(&h1[(k >> 8) & 255], 1u);
        }
        __syncthreads();
        if (tid < 32) {                        // warp-parallel suffix walk
            unsigned a[8]; unsigned lsum = 0;
#pragma unroll
            for (int j = 0; j < 8; ++j) { a[j] = h1[tid * 8 + j]; lsum += a[j]; }
            unsigned s = lsum;
#pragma unroll
            for (int off = 1; off < 32; off <<= 1) {
                unsigned o = __shfl_down_sync(0xFFFFFFFFu, s, off);
                if (tid + off < 32) s += o;
            }
            unsigned above = s - lsum;         // count in higher lanes' bins
            if (above < targ && above + lsum >= targ) {   // unique crossing lane
                unsigned run = above;
                for (int j = 7; j >= 0; --j) {
                    if (run + a[j] >= targ) { s_c1 = (unsigned)(tid * 8 + j); s_t1 = targ - run; break; }
                    run += a[j];
                }
            }
        }
        __syncthreads();
        unsigned pref = bf | (s_c1 << 8);
        unsigned t1 = s_t1;
        h1[tid] = 0u;
        __syncthreads();
        // level 2: histogram of bits [7:0] within the crossing 24-bit prefix
        for (int i = tid; i < cnt; i += 256) {
            unsigned k = (unsigned)(cand[i] >> 32);
            if ((k & 0xFFFFFF00u) == pref) atomicAdd(&h1[k & 255], 1u);
        }
        __syncthreads();
        if (tid < 32) {
            unsigned a[8]; unsigned lsum = 0;
#pragma unroll
            for (int j = 0; j < 8; ++j) { a[j] = h1[tid * 8 + j]; lsum += a[j]; }
            unsigned s = lsum;
#pragma unroll
            for (int off = 1; off < 32; off <<= 1) {
                unsigned o = __shfl_down_sync(0xFFFFFFFFu, s, off);
                if (tid + off < 32) s += o;
            }
            unsigned above = s - lsum;
            if (above < t1 && above + lsum >= t1) {
                unsigned run = above;
                for (int j = 7; j >= 0; --j) {
                    if (run + a[j] >= t1) { s_thresh = pref | (unsigned)(tid * 8 + j); break; }
                    run += a[j];
                }
            }
        }
        __syncthreads();
    }
    unsigned th = s_thresh;                    // 0 when take-all

    // compact survivors into smem (order-free: rank is a multiset count)
    for (int i = tid; i < cnt; i += 256) {
        ull key = cand[i];
        if ((unsigned)(key >> 32) >= th) {
            int p = atomicAdd(&s_cnt2, 1);
            if (p < CAND2) sk2[p] = key;
        }
    }
    __syncthreads();
    int cnt2 = s_cnt2; if (cnt2 > CAND2) cnt2 = CAND2;

    // filtered quadratic rank: this CTA's 256-candidate slice vs survivors
    int i = blockIdx.x * 256 + tid;
    if (i >= cnt) return;
    ull mine = cand[i];
    if ((unsigned)(mine >> 32) < th) return;   // below thresh: rank >= PRE
    int rank = 0, j = 0;
    for (; j + 4 <= cnt2; j += 4) {
        rank += (sk2[j]     > mine);
        rank += (sk2[j + 1] > mine);
        rank += (sk2[j + 2] > mine);
        rank += (sk2[j + 3] > mine);
    }
    for (; j < cnt2; ++j) rank += (sk2[j] > mine);
    if (rank < PRE) g_topkeys[(size_t)b * PRE + rank] = mine;
}

// ---------------- 5) decode selected boxes ----------------
__global__ void decode_kernel(const float* __restrict__ boxp,
                              const float* __restrict__ dirp,
                              const float* __restrict__ anch) {
    int i = blockIdx.x * blockDim.x + threadIdx.x;
    if (i >= BB * PRE) return;
    int b = i / PRE, r = i % PRE;
    ull key = g_topkeys[i];
    unsigned skey = (unsigned)(key >> 32);

    float o[7] = {0.f, 0.f, 0.f, 0.f, 0.f, 0.f, 0.f};
    float4 bb = make_float4(0.f, 0.f, 0.f, 0.f);
    int dl = 0;

    if (skey) {
        unsigned idx = 0xFFFFFFFFu - (unsigned)(key & 0xFFFFFFFFull);
        size_t base = ((size_t)b * NN + idx) * 7;
        float xa = anch[base + 0], ya = anch[base + 1], za = anch[base + 2];
        float wa = anch[base + 3], la = anch[base + 4], ha = anch[base + 5];
        float ra = anch[base + 6];
        float xt = boxp[base + 0], yt = boxp[base + 1], zt = boxp[base + 2];
        float wt = boxp[base + 3], lt = boxp[base + 4], ht = boxp[base + 5];
        float rt = boxp[base + 6];

        za = za + ha * 0.5f;
        float diag = sqrtf(la * la + wa * wa);
        float xg = xt * diag + xa;
        float yg = yt * diag + ya;
        float zg = zt * ha + za;
        float lg = expf(lt) * la;
        float wg = expf(wt) * wa;
        float hg = expf(ht) * ha;
        float rg = rt + ra;
        zg = zg - hg * 0.5f;

        o[0] = xg; o[1] = yg; o[2] = zg; o[3] = wg; o[4] = lg; o[5] = hg; o[6] = rg;

        float cc = fabsf(cosf(rg)), ss = fabsf(sinf(rg));
        float hx = 0.5f * (wg * cc + lg * ss);
        float hy = 0.5f * (wg * ss + lg * cc);
        bb = make_float4(xg - hx, yg - hy, xg + hx, yg + hy);

        size_t dbase = ((size_t)b * NN + idx) * 2;
        dl = (dirp[dbase + 1] > dirp[dbase + 0]) ? 1 : 0;

        atomicOr(&g_validmask[b * WPB + (r >> 6)], 1ull << (r & 63));
    }
#pragma unroll
    for (int j = 0; j < 7; ++j) g_boxes[(size_t)i * 7 + j] = o[j];
    g_bb4[i] = bb;
    g_dl[i] = dl;
}

// ---------------- 6) pairwise IoU bit-matrix (upper triangle, ballot) -------
__global__ void __launch_bounds__(256) iou_kernel() {
    int p = blockIdx.x;          // triangular pair index [0, 528)
    int b = blockIdx.y;
    int rb = (int)((65.0f - sqrtf(4225.0f - 8.0f * (float)p)) * 0.5f);
    while (rb * (65 - rb) / 2 > p) --rb;
    while ((rb + 1) * (64 - rb) / 2 <= p) ++rb;
    int cb = rb + (p - rb * (65 - rb) / 2);

    int t = threadIdx.x;
    __shared__ float4 scol[64]; __shared__ float sca[64];
    __shared__ float4 srow[64]; __shared__ float sra[64];
    if (t < 64) {
        float4 c = g_bb4[(size_t)b * PRE + cb * 64 + t];
        scol[t] = c; sca[t] = (c.z - c.x) * (c.w - c.y);
    } else if (t < 128) {
        int r = t - 64;
        float4 c = g_bb4[(size_t)b * PRE + rb * 64 + r];
        srow[r] = c; sra[r] = (c.z - c.x) * (c.w - c.y);
    }
    __syncthreads();

    int wid = t >> 5, lane = t & 31;
#pragma unroll
    for (int rr = 0; rr < 8; ++rr) {
        int r = wid * 8 + rr;
        int grow = rb * 64 + r;
        float4 rbx = srow[r];
        float  ra  = sra[r];
        ull bits = 0ull;
#pragma unroll
        for (int h = 0; h < 2; ++h) {
            int c = h * 32 + lane;
            int gcol = cb * 64 + c;
            float4 cc = scol[c];
            float ix = fmaxf(0.f, fminf(rbx.z, cc.z) - fmaxf(rbx.x, cc.x));
            float iy = fmaxf(0.f, fminf(rbx.w, cc.w) - fmaxf(rbx.y, cc.y));
            float inter = ix * iy;
            float denom = fmaxf(ra + sca[c] - inter, 1e-8f);
            bool sup = (gcol > grow) && (inter > 0.5f * denom);
            unsigned m = __ballot_sync(0xFFFFFFFFu, sup);
            bits |= (ull)m << (h * 32);
        }
        if (lane == 0)
            g_supmask[((size_t)b * PRE + grow) * WPB + cb] = bits;
    }
}

// ---------------- 7) Jacobi-fixpoint greedy NMS + output (exact) ------------
__global__ void __launch_bounds__(1024) nms_out_kernel(float* __restrict__ out) {
    int b = blockIdx.x, tid = threadIdx.x;
    int w = tid & 31, rg = tid >> 5;   // word index, 64-row group index
    __shared__ ull s_keep[WPB], s_valid[WPB];
    __shared__ ull s_part[WPB][WPB + 1];
    __shared__ int s_flag;
    __shared__ int s_sel[POST];
    __shared__ int s_cnt;

    if (tid < WPB) {
        ull v = g_validmask[b * WPB + tid];
        s_valid[tid] = v;
        s_keep[tid] = v;
    }
    __syncthreads();

    const ull* rowbase = &g_supmask[((size_t)b * PRE + rg * 64) * WPB + w];

    for (int iter = 0; iter < PRE; ++iter) {
        ull acc = 0ull;
        if (w >= rg) {                 // only upper-triangle words are non-zero
            ull kw = s_keep[rg];
#pragma unroll 8
            for (int r = 0; r < 64; ++r)
                if ((kw >> r) & 1ull) acc |= rowbase[(size_t)r * WPB];
        }
        s_part[rg][w] = acc;
        if (tid == 0) s_flag = 0;
        __syncthreads();
        if (tid < WPB) {
            ull o = 0ull;
#pragma unroll
            for (int g = 0; g < WPB; ++g) o |= s_part[g][tid];
            ull nk = s_valid[tid] & ~o;
            if (nk != s_keep[tid]) s_flag = 1;
            s_keep[tid] = nk;
        }
        __syncthreads();
        if (!s_flag) break;
    }

    if (tid == 0) {
        int cnt = 0;
        for (int ww = 0; ww < WPB && cnt < POST; ++ww) {
            ull m = s_keep[ww];
            while (m && cnt < POST) {
                int r = __ffsll((long long)m) - 1;
                m &= m - 1;
                s_sel[cnt++] = ww * 64 + r;
            }
        }
        s_cnt = cnt;
    }
    __syncthreads();

    if (tid < POST) {
        float o0 = 0.f, o1 = 0.f, o2 = 0.f, o3 = 0.f, o4 = 0.f, o5 = 0.f, o6 = 0.f;
        float os = 0.f, om = 0.f;
        if (tid < s_cnt) {
            int r = s_sel[tid];
            const float* bx = &g_boxes[((size_t)b * PRE + r) * 7];
            float x = bx[0], y = bx[1], z = bx[2];
            float wd = bx[3], l = bx[4], h = bx[5], rgr = bx[6];
            float score = __uint_as_float((unsigned)(g_topkeys[(size_t)b * PRE + r] >> 32));
            int dl = g_dl[b * PRE + r];
            const float period = 3.14159265358979323846f;   // 2*pi/NUM_DIR_BINS
            float dir_rot = rgr - floorf(rgr / period) * period;
            float new_r = dir_rot + period * (float)dl;
            bool in_range = (x >= 0.0f) && (y >= -39.68f) && (z >= -5.0f) &&
                            (x <= 69.12f) && (y <= 39.68f) && (z <= 5.0f);
            if (in_range) {
                o0 = x; o1 = y; o2 = z; o3 = wd; o4 = l; o5 = h; o6 = new_r;
                os = score; om = 1.0f;
            }
        }
        size_t bo = (size_t)b * POST + tid;
        out[bo * 7 + 0] = o0; out[bo * 7 + 1] = o1; out[bo * 7 + 2] = o2;
        out[bo * 7 + 3] = o3; out[bo * 7 + 4] = o4; out[bo * 7 + 5] = o5;
        out[bo * 7 + 6] = o6;
        out[BB * POST * 7 + bo]                 = os;   // scores
        out[BB * POST * 7 + BB * POST + bo]     = 0.0f; // labels
        out[BB * POST * 7 + 2 * BB * POST + bo] = om;   // mask
    }
}

// ---------------- launcher: 7 plain launches ----------------
extern "C" void kernel_launch(void* const* d_in, const int* in_sizes, int n_in,
                              void* d_out, int out_size) {
    const float* boxp = (const float*)d_in[0];   // (B,N,7)
    const float* clsp = (const float*)d_in[1];   // (B,N,2)
    const float* dirp = (const float*)d_in[2];   // (B,N,2)
    const float* anch = (const float*)d_in[3];   // (B,N,7)
    float* out = (float*)d_out;

    score_hist_kernel<<<(BB * NN / 2 + 255) / 256, 256>>>((const float4*)clsp);
    scan_kernel<<<BB, 1024>>>();
    compact_kernel<<<(BB * NN / 4 + 255) / 256, 256>>>();
    dim3 grank((CAND + 255) / 256, BB);
    rank3_kernel<<<grank, 256>>>();
    decode_kernel<<<(BB * PRE + 127) / 128, 128>>>(boxp, dirp, anch);
    dim3 giou(528, BB);
    iou_kernel<<<giou, 256>>>();
    nms_out_kernel<<<BB, 1024>>>(out);
}

// round 14
// speedup vs baseline: 1.7991x; 1.1496x over previous
#include <cuda_runtime.h>
#include <math.h>

#define BB    8
#define NN    107136
#define PRE   2048
#define POST  128
#define CAND  6144   // bin-floor candidates ~4600
#define CAND2 3072   // exact-threshold survivors ~2050 (+ties)
#define WPB   32     // 64-bit words per row mask (PRE/64)
#define HB    65536  // 16-bit histogram bins

typedef unsigned long long ull;

// ---------------- scratch (static __device__, no allocations) ----------------
static __device__ unsigned g_skey[BB * NN];
static __device__ unsigned g_hist16[BB * HB];
static __device__ unsigned g_thresh[BB];
static __device__ int      g_target[BB];
static __device__ ull      g_cand[BB * CAND];
static __device__ int      g_cand_cnt[BB];
static __device__ ull      g_topkeys[BB * PRE];
static __device__ float    g_boxes[BB * PRE * 7];
static __device__ float4   g_bb4[BB * PRE];
static __device__ int      g_dl[BB * PRE];
static __device__ ull      g_supmask[(size_t)BB * PRE * WPB];
static __device__ ull      g_validmask[BB * WPB];

// ---------------- 0) zero scratch (full-chip parallelism) ----------------
__global__ void zero_kernel() {
    int i = blockIdx.x * blockDim.x + threadIdx.x;
    if (i < BB * HB / 4) ((uint4*)g_hist16)[i] = make_uint4(0u, 0u, 0u, 0u);
    if (i < BB) { g_cand_cnt[i] = 0; g_thresh[i] = 1u; g_target[i] = 0; }
    if (i < BB * WPB) g_validmask[i] = 0ull;
    if (i < BB * PRE) g_topkeys[i] = 0ull;
}

// ---------------- 1) scores -> keys + 16-bit histogram (ONE expf/elem) ------
__global__ void score_hist_kernel(const float4* __restrict__ cls) {
    int i = blockIdx.x * blockDim.x + threadIdx.x;   // pair index
    if (i >= BB * NN / 2) return;
    int b = (2 * i) / NN;
    float4 c = cls[i];
    float p0, p1;
    {
        float d = c.y - c.x;
        if (d <= 0.0f) { float e = expf(d);  p0 = e / (1.0f + e); }
        else           { float e = expf(-d); p0 = 1.0f / (e + 1.0f); }
    }
    {
        float d = c.w - c.z;
        if (d <= 0.0f) { float e = expf(d);  p1 = e / (1.0f + e); }
        else           { float e = expf(-d); p1 = 1.0f / (e + 1.0f); }
    }
    unsigned k0 = (p0 >= 0.05f) ? __float_as_uint(p0) : 0u;
    unsigned k1 = (p1 >= 0.05f) ? __float_as_uint(p1) : 0u;
    ((uint2*)g_skey)[i] = make_uint2(k0, k1);
    if (k0) atomicAdd(&g_hist16[b * HB + (k0 >> 16)], 1u);
    if (k1) atomicAdd(&g_hist16[b * HB + (k1 >> 16)], 1u);
}

// ---------------- 2) crossing-bin search (read-only; zero_kernel resets) ----
__global__ void __launch_bounds__(1024) scan_kernel() {
    int b = blockIdx.x, tid = threadIdx.x;
    int lane = tid & 31, wid = tid >> 5;
    __shared__ unsigned wsum[32];
    __shared__ unsigned wsuf[32];

    const uint4* h4 = (const uint4*)(g_hist16 + b * HB);
    unsigned tsum = 0;
#pragma unroll
    for (int j = 0; j < 16; ++j) {
        uint4 v = h4[tid * 16 + j];
        tsum += v.x + v.y + v.z + v.w;
    }
    unsigned s = tsum;
#pragma unroll
    for (int off = 1; off < 32; off <<= 1) {
        unsigned o = __shfl_down_sync(0xFFFFFFFFu, s, off);
        if (lane + off < 32) s += o;
    }
    if (lane == 0) wsum[wid] = s;
    __syncthreads();
    if (tid < 32) {
        unsigned t = wsum[tid];
        unsigned e = t;
#pragma unroll
        for (int off = 1; off < 32; off <<= 1) {
            unsigned o = __shfl_down_sync(0xFFFFFFFFu, e, off);
            if (tid + off < 32) e += o;
        }
        wsuf[tid] = e - t;
    }
    __syncthreads();
    unsigned above = wsuf[wid] + (s - tsum);
    if (above < PRE && above + tsum >= PRE) {          // unique crossing thread
        unsigned run = above;
        int found = -1;
        for (int j = 15; j >= 0 && found < 0; --j) {
            uint4 v = h4[tid * 16 + j];
            unsigned a[4] = {v.x, v.y, v.z, v.w};
            for (int q = 3; q >= 0; --q) {
                if (run + a[q] >= PRE) { found = tid * 64 + j * 4 + q; break; }
                run += a[q];
            }
        }
        g_thresh[b] = ((unsigned)found) << 16;         // 16-bit bin floor
        g_target[b] = PRE - (int)run;                  // needed from crossing bin
    }
    // if no crossing (total < PRE): zero_kernel's thresh=1 take-all stands
}

// ---------------- 3) compact candidates (vec4 + warp-aggregated atomic) -----
__global__ void compact_kernel() {
    int i4 = blockIdx.x * blockDim.x + threadIdx.x;
    if (i4 >= BB * NN / 4) return;
    int e0 = i4 * 4;
    int b = e0 / NN;                  // NN % 128 == 0 -> warp-uniform
    unsigned thresh = g_thresh[b];
    uint4 kv = ((const uint4*)g_skey)[i4];
    unsigned k[4] = {kv.x, kv.y, kv.z, kv.w};
    ull loc[4]; int nh = 0;
    unsigned base_i = (unsigned)(e0 - b * NN);
#pragma unroll
    for (int q = 0; q < 4; ++q) {
        if (k[q] && k[q] >= thresh)
            loc[nh++] = ((ull)k[q] << 32) | (ull)(0xFFFFFFFFu - (base_i + q));
    }
    int lane = threadIdx.x & 31;
    int pre = nh;
#pragma unroll
    for (int off = 1; off < 32; off <<= 1) {
        int o = __shfl_up_sync(0xFFFFFFFFu, pre, off);
        if (lane >= off) pre += o;
    }
    int tot = __shfl_sync(0xFFFFFFFFu, pre, 31);
    pre -= nh;
    int base = 0;
    if (lane == 31 && tot > 0) base = atomicAdd(&g_cand_cnt[b], tot);
    base = __shfl_sync(0xFFFFFFFFu, base, 31);
    for (int q = 0; q < nh; ++q) {
        int p = base + pre + q;
        if (p < CAND) g_cand[b * CAND + p] = loc[q];
    }
}

// ---------------- 4) smem-staged redundant-refine + filtered rank -----------
// One global pass stages all candidates into smem; refine histograms, the
// survivor filter, and the vectorized rank loop all run from smem.
// Counting ">mine" over survivors == counting over all candidates (non-
// survivors have score < th <= mine's score), so exactness is preserved.
__global__ void __launch_bounds__(256) rank4_kernel() {
    int b = blockIdx.y, tid = threadIdx.x;
    __shared__ __align__(16) ull ska[CAND];    // 48KB all candidates
    __shared__ __align__(16) ull sk2[CAND2 + 2]; // 24KB survivors (+pad)
    __shared__ unsigned h1[256];
    __shared__ int s_cnt2;
    __shared__ unsigned s_c1, s_t1, s_thresh;

    int cnt = g_cand_cnt[b]; if (cnt > CAND) cnt = CAND;
    if (cnt <= 0) return;                      // topkeys already zeroed
    if (blockIdx.x * 256 >= cnt) return;       // idle slice
    const ull* cand = g_cand + b * CAND;
    unsigned bf = g_thresh[b];

    h1[tid] = 0u;
    if (tid == 0) { s_cnt2 = 0; s_thresh = 0u; s_c1 = 0u; s_t1 = 0u; }
    // single global pass: stage candidates
    for (int i = tid; i < cnt; i += 256) ska[i] = cand[i];
    __syncthreads();

    if (bf > 1u) {
        unsigned targ = (unsigned)g_target[b];
        // level 1: histogram of bits [15:8] within the crossing 16-bit bin
        for (int i = tid; i < cnt; i += 256) {
            unsigned k = (unsigned)(ska[i] >> 32);
            if ((k & 0xFFFF0000u) == bf) atomicAdd(&h1[(k >> 8) & 255], 1u);
        }
        __syncthreads();
        if (tid < 32) {                        // warp-parallel suffix walk
            unsigned a[8]; unsigned lsum = 0;
#pragma unroll
            for (int j = 0; j < 8; ++j) { a[j] = h1[tid * 8 + j]; lsum += a[j]; }
            unsigned s = lsum;
#pragma unroll
            for (int off = 1; off < 32; off <<= 1) {
                unsigned o = __shfl_down_sync(0xFFFFFFFFu, s, off);
                if (tid + off < 32) s += o;
            }
            unsigned above = s - lsum;
            if (above < targ && above + lsum >= targ) {   // unique crossing lane
                unsigned run = above;
                for (int j = 7; j >= 0; --j) {
                    if (run + a[j] >= targ) { s_c1 = (unsigned)(tid * 8 + j); s_t1 = targ - run; break; }
                    run += a[j];
                }
            }
        }
        __syncthreads();
        unsigned pref = bf | (s_c1 << 8);
        unsigned t1 = s_t1;
        h1[tid] = 0u;
        __syncthreads();
        // level 2: histogram of bits [7:0] within the crossing 24-bit prefix
        for (int i = tid; i < cnt; i += 256) {
            unsigned k = (unsigned)(ska[i] >> 32);
            if ((k & 0xFFFFFF00u) == pref) atomicAdd(&h1[k & 255], 1u);
        }
        __syncthreads();
        if (tid < 32) {
            unsigned a[8]; unsigned lsum = 0;
#pragma unroll
            for (int j = 0; j < 8; ++j) { a[j] = h1[tid * 8 + j]; lsum += a[j]; }
            unsigned s = lsum;
#pragma unroll
            for (int off = 1; off < 32; off <<= 1) {
                unsigned o = __shfl_down_sync(0xFFFFFFFFu, s, off);
                if (tid + off < 32) s += o;
            }
            unsigned above = s - lsum;
            if (above < t1 && above + lsum >= t1) {
                unsigned run = above;
                for (int j = 7; j >= 0; --j) {
                    if (run + a[j] >= t1) { s_thresh = pref | (unsigned)(tid * 8 + j); break; }
                    run += a[j];
                }
            }
        }
        __syncthreads();
    }
    unsigned th = s_thresh;                    // 0 when take-all

    // survivor filter (smem -> smem; order-free: rank is a multiset count)
    if (tid < 2) sk2[CAND2 + tid] = 0ull;      // pad for vector tail
    for (int i = tid; i < cnt; i += 256) {
        ull key = ska[i];
        if ((unsigned)(key >> 32) >= th) {
            int p = atomicAdd(&s_cnt2, 1);
            if (p < CAND2) sk2[p] = key;
        }
    }
    __syncthreads();
    int cnt2 = s_cnt2; if (cnt2 > CAND2) cnt2 = CAND2;
    if (tid == 0) { sk2[cnt2] = 0ull; if (cnt2 + 1 < CAND2 + 2) sk2[cnt2 + 1] = 0ull; }
    __syncthreads();

    // vectorized filtered rank: this CTA's slice vs survivors (LDS.128)
    int i = blockIdx.x * 256 + tid;
    if (i >= cnt) return;
    ull mine = ska[i];
    if ((unsigned)(mine >> 32) < th) return;   // below thresh: rank >= PRE
    const ulonglong2* sk22 = (const ulonglong2*)sk2;
    int np = (cnt2 + 1) >> 1;                  // padded to even with zeros
    int rank = 0, j = 0;
    for (; j + 2 <= np; j += 2) {
        ulonglong2 a = sk22[j], c = sk22[j + 1];
        rank += (a.x > mine) + (a.y > mine) + (c.x > mine) + (c.y > mine);
    }
    for (; j < np; ++j) {
        ulonglong2 a = sk22[j];
        rank += (a.x > mine) + (a.y > mine);
    }
    if (rank < PRE) g_topkeys[(size_t)b * PRE + rank] = mine;
}

// ---------------- 5) decode selected boxes ----------------
__global__ void decode_kernel(const float* __restrict__ boxp,
                              const float* __restrict__ dirp,
                              const float* __restrict__ anch) {
    int i = blockIdx.x * blockDim.x + threadIdx.x;
    if (i >= BB * PRE) return;
    int b = i / PRE, r = i % PRE;
    ull key = g_topkeys[i];
    unsigned skey = (unsigned)(key >> 32);

    float o[7] = {0.f, 0.f, 0.f, 0.f, 0.f, 0.f, 0.f};
    float4 bb = make_float4(0.f, 0.f, 0.f, 0.f);
    int dl = 0;

    if (skey) {
        unsigned idx = 0xFFFFFFFFu - (unsigned)(key & 0xFFFFFFFFull);
        size_t base = ((size_t)b * NN + idx) * 7;
        float xa = anch[base + 0], ya = anch[base + 1], za = anch[base + 2];
        float wa = anch[base + 3], la = anch[base + 4], ha = anch[base + 5];
        float ra = anch[base + 6];
        float xt = boxp[base + 0], yt = boxp[base + 1], zt = boxp[base + 2];
        float wt = boxp[base + 3], lt = boxp[base + 4], ht = boxp[base + 5];
        float rt = boxp[base + 6];

        za = za + ha * 0.5f;
        float diag = sqrtf(la * la + wa * wa);
        float xg = xt * diag + xa;
        float yg = yt * diag + ya;
        float zg = zt * ha + za;
        float lg = expf(lt) * la;
        float wg = expf(wt) * wa;
        float hg = expf(ht) * ha;
        float rg = rt + ra;
        zg = zg - hg * 0.5f;

        o[0] = xg; o[1] = yg; o[2] = zg; o[3] = wg; o[4] = lg; o[5] = hg; o[6] = rg;

        float cc = fabsf(cosf(rg)), ss = fabsf(sinf(rg));
        float hx = 0.5f * (wg * cc + lg * ss);
        float hy = 0.5f * (wg * ss + lg * cc);
        bb = make_float4(xg - hx, yg - hy, xg + hx, yg + hy);

        size_t dbase = ((size_t)b * NN + idx) * 2;
        dl = (dirp[dbase + 1] > dirp[dbase + 0]) ? 1 : 0;

        atomicOr(&g_validmask[b * WPB + (r >> 6)], 1ull << (r & 63));
    }
#pragma unroll
    for (int j = 0; j < 7; ++j) g_boxes[(size_t)i * 7 + j] = o[j];
    g_bb4[i] = bb;
    g_dl[i] = dl;
}

// ---------------- 6) pairwise IoU bit-matrix (upper triangle, ballot) -------
__global__ void __launch_bounds__(256) iou_kernel() {
    int p = blockIdx.x;          // triangular pair index [0, 528)
    int b = blockIdx.y;
    int rb = (int)((65.0f - sqrtf(4225.0f - 8.0f * (float)p)) * 0.5f);
    while (rb * (65 - rb) / 2 > p) --rb;
    while ((rb + 1) * (64 - rb) / 2 <= p) ++rb;
    int cb = rb + (p - rb * (65 - rb) / 2);

    int t = threadIdx.x;
    __shared__ float4 scol[64]; __shared__ float sca[64];
    __shared__ float4 srow[64]; __shared__ float sra[64];
    if (t < 64) {
        float4 c = g_bb4[(size_t)b * PRE + cb * 64 + t];
        scol[t] = c; sca[t] = (c.z - c.x) * (c.w - c.y);
    } else if (t < 128) {
        int r = t - 64;
        float4 c = g_bb4[(size_t)b * PRE + rb * 64 + r];
        srow[r] = c; sra[r] = (c.z - c.x) * (c.w - c.y);
    }
    __syncthreads();

    int wid = t >> 5, lane = t & 31;
#pragma unroll
    for (int rr = 0; rr < 8; ++rr) {
        int r = wid * 8 + rr;
        int grow = rb * 64 + r;
        float4 rbx = srow[r];
        float  ra  = sra[r];
        ull bits = 0ull;
#pragma unroll
        for (int h = 0; h < 2; ++h) {
            int c = h * 32 + lane;
            int gcol = cb * 64 + c;
            float4 cc = scol[c];
            float ix = fmaxf(0.f, fminf(rbx.z, cc.z) - fmaxf(rbx.x, cc.x));
            float iy = fmaxf(0.f, fminf(rbx.w, cc.w) - fmaxf(rbx.y, cc.y));
            float inter = ix * iy;
            float denom = fmaxf(ra + sca[c] - inter, 1e-8f);
            bool sup = (gcol > grow) && (inter > 0.5f * denom);
            unsigned m = __ballot_sync(0xFFFFFFFFu, sup);
            bits |= (ull)m << (h * 32);
        }
        if (lane == 0)
            g_supmask[((size_t)b * PRE + grow) * WPB + cb] = bits;
    }
}

// ---------------- 7) Jacobi-fixpoint greedy NMS + output (exact) ------------
__global__ void __launch_bounds__(1024) nms_out_kernel(float* __restrict__ out) {
    int b = blockIdx.x, tid = threadIdx.x;
    int w = tid & 31, rg = tid >> 5;   // word index, 64-row group index
    __shared__ ull s_keep[WPB], s_valid[WPB];
    __shared__ ull s_part[WPB][WPB + 1];
    __shared__ int s_flag;
    __shared__ int s_sel[POST];
    __shared__ int s_cnt;

    if (tid < WPB) {
        ull v = g_validmask[b * WPB + tid];
        s_valid[tid] = v;
        s_keep[tid] = v;
    }
    __syncthreads();

    const ull* rowbase = &g_supmask[((size_t)b * PRE + rg * 64) * WPB + w];

    for (int iter = 0; iter < PRE; ++iter) {
        ull acc = 0ull;
        if (w >= rg) {                 // only upper-triangle words are non-zero
            ull kw = s_keep[rg];
#pragma unroll 8
            for (int r = 0; r < 64; ++r)
                if ((kw >> r) & 1ull) acc |= rowbase[(size_t)r * WPB];
        }
        s_part[rg][w] = acc;
        if (tid == 0) s_flag = 0;
        __syncthreads();
        if (tid < WPB) {
            ull o = 0ull;
#pragma unroll
            for (int g = 0; g < WPB; ++g) o |= s_part[g][tid];
            ull nk = s_valid[tid] & ~o;
            if (nk != s_keep[tid]) s_flag = 1;
            s_keep[tid] = nk;
        }
        __syncthreads();
        if (!s_flag) break;
    }

    if (tid == 0) {
        int cnt = 0;
        for (int ww = 0; ww < WPB && cnt < POST; ++ww) {
            ull m = s_keep[ww];
            while (m && cnt < POST) {
                int r = __ffsll((long long)m) - 1;
                m &= m - 1;
                s_sel[cnt++] = ww * 64 + r;
            }
        }
        s_cnt = cnt;
    }
    __syncthreads();

    if (tid < POST) {
        float o0 = 0.f, o1 = 0.f, o2 = 0.f, o3 = 0.f, o4 = 0.f, o5 = 0.f, o6 = 0.f;
        float os = 0.f, om = 0.f;
        if (tid < s_cnt) {
            int r = s_sel[tid];
            const float* bx = &g_boxes[((size_t)b * PRE + r) * 7];
            float x = bx[0], y = bx[1], z = bx[2];
            float wd = bx[3], l = bx[4], h = bx[5], rgr = bx[6];
            float score = __uint_as_float((unsigned)(g_topkeys[(size_t)b * PRE + r] >> 32));
            int dl = g_dl[b * PRE + r];
            const float period = 3.14159265358979323846f;   // 2*pi/NUM_DIR_BINS
            float dir_rot = rgr - floorf(rgr / period) * period;
            float new_r = dir_rot + period * (float)dl;
            bool in_range = (x >= 0.0f) && (y >= -39.68f) && (z >= -5.0f) &&
                            (x <= 69.12f) && (y <= 39.68f) && (z <= 5.0f);
            if (in_range) {
                o0 = x; o1 = y; o2 = z; o3 = wd; o4 = l; o5 = h; o6 = new_r;
                os = score; om = 1.0f;
            }
        }
        size_t bo = (size_t)b * POST + tid;
        out[bo * 7 + 0] = o0; out[bo * 7 + 1] = o1; out[bo * 7 + 2] = o2;
        out[bo * 7 + 3] = o3; out[bo * 7 + 4] = o4; out[bo * 7 + 5] = o5;
        out[bo * 7 + 6] = o6;
        out[BB * POST * 7 + bo]                 = os;   // scores
        out[BB * POST * 7 + BB * POST + bo]     = 0.0f; // labels
        out[BB * POST * 7 + 2 * BB * POST + bo] = om;   // mask
    }
}

// ---------------- launcher: 8 plain launches ----------------
extern "C" void kernel_launch(void* const* d_in, const int* in_sizes, int n_in,
                              void* d_out, int out_size) {
    const float* boxp = (const float*)d_in[0];   // (B,N,7)
    const float* clsp = (const float*)d_in[1];   // (B,N,2)
    const float* dirp = (const float*)d_in[2];   // (B,N,2)
    const float* anch = (const float*)d_in[3];   // (B,N,7)
    float* out = (float*)d_out;

    zero_kernel<<<(BB * HB / 4 + 255) / 256, 256>>>();
    score_hist_kernel<<<(BB * NN / 2 + 255) / 256, 256>>>((const float4*)clsp);
    scan_kernel<<<BB, 1024>>>();
    compact_kernel<<<(BB * NN / 4 + 255) / 256, 256>>>();
    dim3 grank((CAND + 255) / 256, BB);
    rank4_kernel<<<grank, 256>>>();
    decode_kernel<<<(BB * PRE + 127) / 128, 128>>>(boxp, dirp, anch);
    dim3 giou(528, BB);
    iou_kernel<<<giou, 256>>>();
    nms_out_kernel<<<BB, 1024>>>(out);
}

// round 15
// speedup vs baseline: 1.8670x; 1.0377x over previous
#include <cuda_runtime.h>
#include <math.h>

#define BB    8
#define NN    107136
#define PRE   2048
#define POST  128
#define CAND  6144   // bin-floor candidates ~4600
#define CAND2 3072   // exact-threshold survivors ~2050 (+ties)
#define WPB   32     // 64-bit words per row mask (PRE/64)
#define HB    65536  // 16-bit histogram bins

typedef unsigned long long ull;

// PDL intrinsics
__device__ __forceinline__ void pdl_launch_dependents() {
    asm volatile("griddepcontrol.launch_dependents;");
}
__device__ __forceinline__ void pdl_wait() {
    asm volatile("griddepcontrol.wait;" ::: "memory");
}

// ---------------- scratch (static __device__, no allocations) ----------------
// hist16 zeroed by compact_kernel (full-chip) after scan's last read, so every
// replay starts clean (static init is also zero).
static __device__ unsigned g_skey[BB * NN];
static __device__ unsigned g_hist16[BB * HB];
static __device__ unsigned g_thresh[BB];
static __device__ int      g_target[BB];
static __device__ ull      g_cand[BB * CAND];
static __device__ int      g_cand_cnt[BB];
static __device__ ull      g_topkeys[BB * PRE];
static __device__ float    g_boxes[BB * PRE * 7];
static __device__ float4   g_bb4[BB * PRE];
static __device__ int      g_dl[BB * PRE];
static __device__ ull      g_supmask[(size_t)BB * PRE * WPB];
static __device__ ull      g_validmask[BB * WPB];

// ---------------- 1) scores -> keys + 16-bit histogram (ONE expf/elem) ------
__global__ void score_hist_kernel(const float4* __restrict__ cls) {
    pdl_launch_dependents();                         // let scan park early
    int i = blockIdx.x * blockDim.x + threadIdx.x;   // pair index
    if (i >= BB * NN / 2) return;
    int b = (2 * i) / NN;
    float4 c = cls[i];
    float p0, p1;
    {
        float d = c.y - c.x;
        if (d <= 0.0f) { float e = expf(d);  p0 = e / (1.0f + e); }
        else           { float e = expf(-d); p0 = 1.0f / (e + 1.0f); }
    }
    {
        float d = c.w - c.z;
        if (d <= 0.0f) { float e = expf(d);  p1 = e / (1.0f + e); }
        else           { float e = expf(-d); p1 = 1.0f / (e + 1.0f); }
    }
    unsigned k0 = (p0 >= 0.05f) ? __float_as_uint(p0) : 0u;
    unsigned k1 = (p1 >= 0.05f) ? __float_as_uint(p1) : 0u;
    ((uint2*)g_skey)[i] = make_uint2(k0, k1);
    if (k0) atomicAdd(&g_hist16[b * HB + (k0 >> 16)], 1u);
    if (k1) atomicAdd(&g_hist16[b * HB + (k1 >> 16)], 1u);
}

// ---------------- 2) crossing-bin search + small state resets (PDL) ---------
__global__ void __launch_bounds__(1024) scan_kernel() {
    int b = blockIdx.x, tid = threadIdx.x;
    int lane = tid & 31, wid = tid >> 5;
    __shared__ unsigned wsum[32];
    __shared__ unsigned wsuf[32];
    __shared__ unsigned s_total;

    // pre-wait preamble: reset state consumed only by LATER phases of this replay
    if (tid == 0) g_cand_cnt[b] = 0;
    if (tid < WPB) g_validmask[b * WPB + tid] = 0ull;
    for (int i = tid; i < PRE; i += 1024) g_topkeys[(size_t)b * PRE + i] = 0ull;

    pdl_wait();   // histogram from score_hist must be complete

    const uint4* h4 = (const uint4*)(g_hist16 + b * HB);
    unsigned tsum = 0;
#pragma unroll
    for (int j = 0; j < 16; ++j) {
        uint4 v = h4[tid * 16 + j];
        tsum += v.x + v.y + v.z + v.w;
    }
    unsigned s = tsum;
#pragma unroll
    for (int off = 1; off < 32; off <<= 1) {
        unsigned o = __shfl_down_sync(0xFFFFFFFFu, s, off);
        if (lane + off < 32) s += o;
    }
    if (lane == 0) wsum[wid] = s;
    __syncthreads();
    if (tid < 32) {
        unsigned t = wsum[tid];
        unsigned e = t;
#pragma unroll
        for (int off = 1; off < 32; off <<= 1) {
            unsigned o = __shfl_down_sync(0xFFFFFFFFu, e, off);
            if (tid + off < 32) e += o;
        }
        wsuf[tid] = e - t;
        if (tid == 0) s_total = e;
    }
    __syncthreads();
    if (tid == 0 && s_total < PRE) { g_thresh[b] = 1u; g_target[b] = 0; }  // take-all
    unsigned above = wsuf[wid] + (s - tsum);
    if (above < PRE && above + tsum >= PRE) {          // unique crossing thread
        unsigned run = above;
        int found = -1;
        for (int j = 15; j >= 0 && found < 0; --j) {
            uint4 v = h4[tid * 16 + j];
            unsigned a[4] = {v.x, v.y, v.z, v.w};
            for (int q = 3; q >= 0; --q) {
                if (run + a[q] >= PRE) { found = tid * 64 + j * 4 + q; break; }
                run += a[q];
            }
        }
        g_thresh[b] = ((unsigned)found) << 16;         // 16-bit bin floor
        g_target[b] = PRE - (int)run;                  // needed from crossing bin
    }
}

// ---------------- 3) compact candidates + full-chip hist16 zeroing ----------
__global__ void compact_kernel() {
    int gtid = blockIdx.x * blockDim.x + threadIdx.x;
    // zero hist16 for next replay (scan already consumed it; full parallelism)
    if (gtid < BB * HB / 4) ((uint4*)g_hist16)[gtid] = make_uint4(0u, 0u, 0u, 0u);

    int i4 = gtid;
    if (i4 >= BB * NN / 4) return;
    int e0 = i4 * 4;
    int b = e0 / NN;                  // NN % 128 == 0 -> warp-uniform
    unsigned thresh = g_thresh[b];
    uint4 kv = ((const uint4*)g_skey)[i4];
    unsigned k[4] = {kv.x, kv.y, kv.z, kv.w};
    ull loc[4]; int nh = 0;
    unsigned base_i = (unsigned)(e0 - b * NN);
#pragma unroll
    for (int q = 0; q < 4; ++q) {
        if (k[q] && k[q] >= thresh)
            loc[nh++] = ((ull)k[q] << 32) | (ull)(0xFFFFFFFFu - (base_i + q));
    }
    int lane = threadIdx.x & 31;
    int pre = nh;
#pragma unroll
    for (int off = 1; off < 32; off <<= 1) {
        int o = __shfl_up_sync(0xFFFFFFFFu, pre, off);
        if (lane >= off) pre += o;
    }
    int tot = __shfl_sync(0xFFFFFFFFu, pre, 31);
    pre -= nh;
    int base = 0;
    if (lane == 31 && tot > 0) base = atomicAdd(&g_cand_cnt[b], tot);
    base = __shfl_sync(0xFFFFFFFFu, base, 31);
    for (int q = 0; q < nh; ++q) {
        int p = base + pre + q;
        if (p < CAND) g_cand[b * CAND + p] = loc[q];
    }
}

// ---------------- 4) smem-staged redundant-refine + filtered rank -----------
__global__ void __launch_bounds__(256) rank4_kernel() {
    pdl_launch_dependents();                   // let decode park early
    int b = blockIdx.y, tid = threadIdx.x;
    __shared__ __align__(16) ull ska[CAND];    // 48KB all candidates
    __shared__ __align__(16) ull sk2[CAND2 + 2]; // 24KB survivors (+pad)
    __shared__ unsigned h1[256];
    __shared__ int s_cnt2;
    __shared__ unsigned s_c1, s_t1, s_thresh;

    int cnt = g_cand_cnt[b]; if (cnt > CAND) cnt = CAND;
    if (cnt <= 0) return;                      // topkeys already zeroed
    if (blockIdx.x * 256 >= cnt) return;       // idle slice
    const ull* cand = g_cand + b * CAND;
    unsigned bf = g_thresh[b];

    h1[tid] = 0u;
    if (tid == 0) { s_cnt2 = 0; s_thresh = 0u; s_c1 = 0u; s_t1 = 0u; }
    // single global pass: stage candidates
    for (int i = tid; i < cnt; i += 256) ska[i] = cand[i];
    __syncthreads();

    if (bf > 1u) {
        unsigned targ = (unsigned)g_target[b];
        // level 1: histogram of bits [15:8] within the crossing 16-bit bin
        for (int i = tid; i < cnt; i += 256) {
            unsigned k = (unsigned)(ska[i] >> 32);
            if ((k & 0xFFFF0000u) == bf) atomicAdd(&h1[(k >> 8) & 255], 1u);
        }
        __syncthreads();
        if (tid < 32) {                        // warp-parallel suffix walk
            unsigned a[8]; unsigned lsum = 0;
#pragma unroll
            for (int j = 0; j < 8; ++j) { a[j] = h1[tid * 8 + j]; lsum += a[j]; }
            unsigned s = lsum;
#pragma unroll
            for (int off = 1; off < 32; off <<= 1) {
                unsigned o = __shfl_down_sync(0xFFFFFFFFu, s, off);
                if (tid + off < 32) s += o;
            }
            unsigned above = s - lsum;
            if (above < targ && above + lsum >= targ) {   // unique crossing lane
                unsigned run = above;
                for (int j = 7; j >= 0; --j) {
                    if (run + a[j] >= targ) { s_c1 = (unsigned)(tid * 8 + j); s_t1 = targ - run; break; }
                    run += a[j];
                }
            }
        }
        __syncthreads();
        unsigned pref = bf | (s_c1 << 8);
        unsigned t1 = s_t1;
        h1[tid] = 0u;
        __syncthreads();
        // level 2: histogram of bits [7:0] within the crossing 24-bit prefix
        for (int i = tid; i < cnt; i += 256) {
            unsigned k = (unsigned)(ska[i] >> 32);
            if ((k & 0xFFFFFF00u) == pref) atomicAdd(&h1[k & 255], 1u);
        }
        __syncthreads();
        if (tid < 32) {
            unsigned a[8]; unsigned lsum = 0;
#pragma unroll
            for (int j = 0; j < 8; ++j) { a[j] = h1[tid * 8 + j]; lsum += a[j]; }
            unsigned s = lsum;
#pragma unroll
            for (int off = 1; off < 32; off <<= 1) {
                unsigned o = __shfl_down_sync(0xFFFFFFFFu, s, off);
                if (tid + off < 32) s += o;
            }
            unsigned above = s - lsum;
            if (above < t1 && above + lsum >= t1) {
                unsigned run = above;
                for (int j = 7; j >= 0; --j) {
                    if (run + a[j] >= t1) { s_thresh = pref | (unsigned)(tid * 8 + j); break; }
                    run += a[j];
                }
            }
        }
        __syncthreads();
    }
    unsigned th = s_thresh;                    // 0 when take-all

    // survivor filter (smem -> smem; order-free: rank is a multiset count)
    if (tid < 2) sk2[CAND2 + tid] = 0ull;      // pad for vector tail
    for (int i = tid; i < cnt; i += 256) {
        ull key = ska[i];
        if ((unsigned)(key >> 32) >= th) {
            int p = atomicAdd(&s_cnt2, 1);
            if (p < CAND2) sk2[p] = key;
        }
    }
    __syncthreads();
    int cnt2 = s_cnt2; if (cnt2 > CAND2) cnt2 = CAND2;
    if (tid == 0) { sk2[cnt2] = 0ull; if (cnt2 + 1 < CAND2 + 2) sk2[cnt2 + 1] = 0ull; }
    __syncthreads();

    // vectorized filtered rank: this CTA's slice vs survivors (LDS.128)
    int i = blockIdx.x * 256 + tid;
    if (i >= cnt) return;
    ull mine = ska[i];
    if ((unsigned)(mine >> 32) < th) return;   // below thresh: rank >= PRE
    const ulonglong2* sk22 = (const ulonglong2*)sk2;
    int np = (cnt2 + 1) >> 1;                  // padded to even with zeros
    int rank = 0, j = 0;
    for (; j + 2 <= np; j += 2) {
        ulonglong2 a = sk22[j], c = sk22[j + 1];
        rank += (a.x > mine) + (a.y > mine) + (c.x > mine) + (c.y > mine);
    }
    for (; j < np; ++j) {
        ulonglong2 a = sk22[j];
        rank += (a.x > mine) + (a.y > mine);
    }
    if (rank < PRE) g_topkeys[(size_t)b * PRE + rank] = mine;
}

// ---------------- 5) decode selected boxes (PDL successor) ----------------
__global__ void decode_kernel(const float* __restrict__ boxp,
                              const float* __restrict__ dirp,
                              const float* __restrict__ anch) {
    int i = blockIdx.x * blockDim.x + threadIdx.x;
    if (i >= BB * PRE) return;
    int b = i / PRE, r = i % PRE;
    pdl_wait();                       // topkeys from rank must be complete
    ull key = g_topkeys[i];
    unsigned skey = (unsigned)(key >> 32);

    float o[7] = {0.f, 0.f, 0.f, 0.f, 0.f, 0.f, 0.f};
    float4 bb = make_float4(0.f, 0.f, 0.f, 0.f);
    int dl = 0;

    if (skey) {
        unsigned idx = 0xFFFFFFFFu - (unsigned)(key & 0xFFFFFFFFull);
        size_t base = ((size_t)b * NN + idx) * 7;
        float xa = anch[base + 0], ya = anch[base + 1], za = anch[base + 2];
        float wa = anch[base + 3], la = anch[base + 4], ha = anch[base + 5];
        float ra = anch[base + 6];
        float xt = boxp[base + 0], yt = boxp[base + 1], zt = boxp[base + 2];
        float wt = boxp[base + 3], lt = boxp[base + 4], ht = boxp[base + 5];
        float rt = boxp[base + 6];

        za = za + ha * 0.5f;
        float diag = sqrtf(la * la + wa * wa);
        float xg = xt * diag + xa;
        float yg = yt * diag + ya;
        float zg = zt * ha + za;
        float lg = expf(lt) * la;
        float wg = expf(wt) * wa;
        float hg = expf(ht) * ha;
        float rg = rt + ra;
        zg = zg - hg * 0.5f;

        o[0] = xg; o[1] = yg; o[2] = zg; o[3] = wg; o[4] = lg; o[5] = hg; o[6] = rg;

        float cc = fabsf(cosf(rg)), ss = fabsf(sinf(rg));
        float hx = 0.5f * (wg * cc + lg * ss);
        float hy = 0.5f * (wg * ss + lg * cc);
        bb = make_float4(xg - hx, yg - hy, xg + hx, yg + hy);

        size_t dbase = ((size_t)b * NN + idx) * 2;
        dl = (dirp[dbase + 1] > dirp[dbase + 0]) ? 1 : 0;

        atomicOr(&g_validmask[b * WPB + (r >> 6)], 1ull << (r & 63));
    }
#pragma unroll
    for (int j = 0; j < 7; ++j) g_boxes[(size_t)i * 7 + j] = o[j];
    g_bb4[i] = bb;
    g_dl[i] = dl;
}

// ---------------- 6) pairwise IoU bit-matrix (upper triangle, ballot) -------
__global__ void __launch_bounds__(256) iou_kernel() {
    pdl_launch_dependents();     // let nms_out park early
    int p = blockIdx.x;          // triangular pair index [0, 528)
    int b = blockIdx.y;
    int rb = (int)((65.0f - sqrtf(4225.0f - 8.0f * (float)p)) * 0.5f);
    while (rb * (65 - rb) / 2 > p) --rb;
    while ((rb + 1) * (64 - rb) / 2 <= p) ++rb;
    int cb = rb + (p - rb * (65 - rb) / 2);

    int t = threadIdx.x;
    __shared__ float4 scol[64]; __shared__ float sca[64];
    __shared__ float4 srow[64]; __shared__ float sra[64];
    if (t < 64) {
        float4 c = g_bb4[(size_t)b * PRE + cb * 64 + t];
        scol[t] = c; sca[t] = (c.z - c.x) * (c.w - c.y);
    } else if (t < 128) {
        int r = t - 64;
        float4 c = g_bb4[(size_t)b * PRE + rb * 64 + r];
        srow[r] = c; sra[r] = (c.z - c.x) * (c.w - c.y);
    }
    __syncthreads();

    int wid = t >> 5, lane = t & 31;
#pragma unroll
    for (int rr = 0; rr < 8; ++rr) {
        int r = wid * 8 + rr;
        int grow = rb * 64 + r;
        float4 rbx = srow[r];
        float  ra  = sra[r];
        ull bits = 0ull;
#pragma unroll
        for (int h = 0; h < 2; ++h) {
            int c = h * 32 + lane;
            int gcol = cb * 64 + c;
            float4 cc = scol[c];
            float ix = fmaxf(0.f, fminf(rbx.z, cc.z) - fmaxf(rbx.x, cc.x));
            float iy = fmaxf(0.f, fminf(rbx.w, cc.w) - fmaxf(rbx.y, cc.y));
            float inter = ix * iy;
            float denom = fmaxf(ra + sca[c] - inter, 1e-8f);
            bool sup = (gcol > grow) && (inter > 0.5f * denom);
            unsigned m = __ballot_sync(0xFFFFFFFFu, sup);
            bits |= (ull)m << (h * 32);
        }
        if (lane == 0)
            g_supmask[((size_t)b * PRE + grow) * WPB + cb] = bits;
    }
}

// ---------------- 7) Jacobi-fixpoint greedy NMS + output (PDL successor) ----
__global__ void __launch_bounds__(1024) nms_out_kernel(float* __restrict__ out) {
    int b = blockIdx.x, tid = threadIdx.x;
    int w = tid & 31, rg = tid >> 5;   // word index, 64-row group index
    __shared__ ull s_keep[WPB], s_valid[WPB];
    __shared__ ull s_part[WPB][WPB + 1];
    __shared__ int s_flag;
    __shared__ int s_sel[POST];
    __shared__ int s_cnt;

    pdl_wait();                        // supmask from iou must be complete
    if (tid < WPB) {
        ull v = g_validmask[b * WPB + tid];
        s_valid[tid] = v;
        s_keep[tid] = v;
    }
    __syncthreads();

    const ull* rowbase = &g_supmask[((size_t)b * PRE + rg * 64) * WPB + w];

    for (int iter = 0; iter < PRE; ++iter) {
        ull acc = 0ull;
        if (w >= rg) {                 // only upper-triangle words are non-zero
            ull kw = s_keep[rg];
#pragma unroll 8
            for (int r = 0; r < 64; ++r)
                if ((kw >> r) & 1ull) acc |= rowbase[(size_t)r * WPB];
        }
        s_part[rg][w] = acc;
        if (tid == 0) s_flag = 0;
        __syncthreads();
        if (tid < WPB) {
            ull o = 0ull;
#pragma unroll
            for (int g = 0; g < WPB; ++g) o |= s_part[g][tid];
            ull nk = s_valid[tid] & ~o;
            if (nk != s_keep[tid]) s_flag = 1;
            s_keep[tid] = nk;
        }
        __syncthreads();
        if (!s_flag) break;
    }

    if (tid == 0) {
        int cnt = 0;
        for (int ww = 0; ww < WPB && cnt < POST; ++ww) {
            ull m = s_keep[ww];
            while (m && cnt < POST) {
                int r = __ffsll((long long)m) - 1;
                m &= m - 1;
                s_sel[cnt++] = ww * 64 + r;
            }
        }
        s_cnt = cnt;
    }
    __syncthreads();

    if (tid < POST) {
        float o0 = 0.f, o1 = 0.f, o2 = 0.f, o3 = 0.f, o4 = 0.f, o5 = 0.f, o6 = 0.f;
        float os = 0.f, om = 0.f;
        if (tid < s_cnt) {
            int r = s_sel[tid];
            const float* bx = &g_boxes[((size_t)b * PRE + r) * 7];
            float x = bx[0], y = bx[1], z = bx[2];
            float wd = bx[3], l = bx[4], h = bx[5], rgr = bx[6];
            float score = __uint_as_float((unsigned)(g_topkeys[(size_t)b * PRE + r] >> 32));
            int dl = g_dl[b * PRE + r];
            const float period = 3.14159265358979323846f;   // 2*pi/NUM_DIR_BINS
            float dir_rot = rgr - floorf(rgr / period) * period;
            float new_r = dir_rot + period * (float)dl;
            bool in_range = (x >= 0.0f) && (y >= -39.68f) && (z >= -5.0f) &&
                            (x <= 69.12f) && (y <= 39.68f) && (z <= 5.0f);
            if (in_range) {
                o0 = x; o1 = y; o2 = z; o3 = wd; o4 = l; o5 = h; o6 = new_r;
                os = score; om = 1.0f;
            }
        }
        size_t bo = (size_t)b * POST + tid;
        out[bo * 7 + 0] = o0; out[bo * 7 + 1] = o1; out[bo * 7 + 2] = o2;
        out[bo * 7 + 3] = o3; out[bo * 7 + 4] = o4; out[bo * 7 + 5] = o5;
        out[bo * 7 + 6] = o6;
        out[BB * POST * 7 + bo]                 = os;   // scores
        out[BB * POST * 7 + BB * POST + bo]     = 0.0f; // labels
        out[BB * POST * 7 + 2 * BB * POST + bo] = om;   // mask
    }
}

// ---------------- launcher: 7 launches; PDL only on small-grid successors ---
extern "C" void kernel_launch(void* const* d_in, const int* in_sizes, int n_in,
                              void* d_out, int out_size) {
    const float* boxp = (const float*)d_in[0];   // (B,N,7)
    const float* clsp = (const float*)d_in[1];   // (B,N,2)
    const float* dirp = (const float*)d_in[2];   // (B,N,2)
    const float* anch = (const float*)d_in[3];   // (B,N,7)
    float* out = (float*)d_out;

    cudaLaunchAttribute attr;
    attr.id = cudaLaunchAttributeProgrammaticStreamSerialization;
    attr.val.programmaticStreamSerializationAllowed = 1;
    cudaLaunchConfig_t cfg = {};
    cfg.attrs = &attr;
    cfg.numAttrs = 1;

    score_hist_kernel<<<(BB * NN / 2 + 255) / 256, 256>>>((const float4*)clsp);

    cfg.gridDim = dim3(BB); cfg.blockDim = dim3(1024);
    cudaLaunchKernelEx(&cfg, scan_kernel);           // PDL: parks during score_hist

    compact_kernel<<<(BB * NN / 4 + 255) / 256, 256>>>();

    dim3 grank((CAND + 255) / 256, BB);
    rank4_kernel<<<grank, 256>>>();

    cfg.gridDim = dim3((BB * PRE + 127) / 128); cfg.blockDim = dim3(128);
    cudaLaunchKernelEx(&cfg, decode_kernel, boxp, dirp, anch);  // PDL: parks during rank

    dim3 giou(528, BB);
    iou_kernel<<<giou, 256>>>();

    cfg.gridDim = dim3(BB); cfg.blockDim = dim3(1024);
    cudaLaunchKernelEx(&cfg, nms_out_kernel, out);   // PDL: parks during iou
}